// round 8
// baseline (speedup 1.0000x reference)
#include <cuda_runtime.h>
#include <cuda_bf16.h>
#include <cuda_fp16.h>
#include <cstdint>

#define B_    4
#define C_    256
#define H_    128
#define W_    128
#define HW_   (H_*W_)
#define COMP_ 64
#define KK_   25
#define HO_   64
#define WO_   64

// Scratch (device globals; allocation is forbidden)
// g_comp layout: [b][px (h*W+w)][ch]  (channel-minor!)
__device__ float g_comp[B_*HW_*COMP_];
__device__ float g_mask[B_*KK_*HO_*WO_];                    // NORMALIZED softmax weights
__device__ __align__(16) unsigned char g_w1b[COMP_*C_*2];   // w1 bf16, plain [n][k]
__device__ __align__(16) __half g_xh[B_*C_*HW_];            // fp16 shadow of x (32MB)

__device__ __forceinline__ uint32_t smem_u32(const void* p) {
    uint32_t a;
    asm("{ .reg .u64 t; cvta.to.shared.u64 t, %1; cvt.u32.u64 %0, t; }" : "=r"(a) : "l"(p));
    return a;
}

// ================= Kernel P: w1 fp32 -> bf16 =================
__global__ void k_prep(const float* __restrict__ w1) {
    int idx = blockIdx.x * 256 + threadIdx.x;
    if (idx < COMP_ * C_)
        ((__nv_bfloat16*)g_w1b)[idx] = __float2bfloat16(w1[idx]);
}

// ================= Kernel A: 1x1 conv via mma.sync bf16 (+ emit fp16 x copy) =================
#define XS_OFF   0
#define WS_OFF   32768
#define BIAS_OFF 65536
#define A_SMEM_BYTES (65536 + 256)

__global__ __launch_bounds__(256) void k_conv1(const float* __restrict__ x,
                                               const float* __restrict__ b1) {
    extern __shared__ __align__(16) char sm[];
    const uint32_t smb = smem_u32(sm);
    const int tid  = threadIdx.x;
    const int warp = tid >> 5;
    const int lane = tid & 31;
    const int b    = blockIdx.y;
    const int px0  = blockIdx.x * 256;

    {
        const uint32_t* wsrc = (const uint32_t*)g_w1b;
        for (int i = tid; i < COMP_ * C_ / 2; i += 256) {
            int n = i >> 7, u = i & 127;
            int cx = u >> 2;
            uint32_t off = WS_OFF + n*512 + (uint32_t)((cx ^ (n & 7)) << 4) + (u & 3) * 4;
            *(uint32_t*)(sm + off) = wsrc[i];
        }
        if (tid < 64) ((float*)(sm + BIAS_OFF))[tid] = b1[tid];
    }

    float acc[2][8][4];
#pragma unroll
    for (int mt = 0; mt < 2; mt++)
#pragma unroll
        for (int nt = 0; nt < 8; nt++)
#pragma unroll
            for (int i = 0; i < 4; i++) acc[mt][nt][i] = 0.f;

    const int lj  = lane & 7;
    const int lg2 = (lane >> 3) & 1;
    const int lg4 = lane >> 4;
    const int g_  = lane >> 2;
    const int tig = lane & 3;

    const float* xbase = x + ((size_t)b * C_) * HW_ + px0;

    for (int chunk = 0; chunk < 4; chunk++) {
        __syncthreads();
        const float4* xsrc = (const float4*)(xbase + (size_t)(chunk * 64) * HW_);
#pragma unroll
        for (int l = 0; l < 16; l++) {
            int id = l * 256 + tid;
            int ch = id >> 6, f4 = id & 63;
            float4 v = xsrc[(size_t)ch * (HW_/4) + f4];
            __nv_bfloat162 h0 = __float22bfloat162_rn(make_float2(v.x, v.y));
            __nv_bfloat162 h1 = __float22bfloat162_rn(make_float2(v.z, v.w));
            int cx = f4 >> 1;
            uint32_t off = XS_OFF + ch*512 + (uint32_t)((cx ^ (ch & 7)) << 4) + (f4 & 1) * 8;
            *(uint2*)(sm + off) = make_uint2(*(uint32_t*)&h0, *(uint32_t*)&h1);
            // fp16 shadow copy for carafe (coalesced 8B stores)
            __half2 f0 = __floats2half2_rn(v.x, v.y);
            __half2 f1 = __floats2half2_rn(v.z, v.w);
            size_t goff = ((size_t)(b*C_ + chunk*64 + ch))*HW_ + px0 + f4*4;
            *(uint2*)&g_xh[goff] = make_uint2(*(uint32_t*)&f0, *(uint32_t*)&f1);
        }
        __syncthreads();

#pragma unroll
        for (int s = 0; s < 4; s++) {
            uint32_t a[2][4];
            const int krow = s*16 + lj + lg4*8;
#pragma unroll
            for (int mt = 0; mt < 2; mt++) {
                int pxcol = warp*32 + mt*16 + lg2*8;
                uint32_t addr = smb + XS_OFF + krow*512
                              + (uint32_t)(((pxcol >> 3) ^ (krow & 7)) << 4);
                asm volatile("ldmatrix.sync.aligned.m8n8.x4.trans.shared.b16 "
                             "{%0,%1,%2,%3}, [%4];"
                             : "=r"(a[mt][0]), "=r"(a[mt][1]), "=r"(a[mt][2]), "=r"(a[mt][3])
                             : "r"(addr));
            }
            const int kabs = chunk*64 + s*16;
            const int cx0  = kabs >> 3;
#pragma unroll
            for (int nt = 0; nt < 8; nt++) {
                int n = nt*8 + g_;
                uint32_t ab0 = smb + WS_OFF + n*512
                             + (uint32_t)(((cx0     ) ^ (n & 7)) << 4) + tig*4;
                uint32_t ab1 = smb + WS_OFF + n*512
                             + (uint32_t)(((cx0 + 1) ^ (n & 7)) << 4) + tig*4;
                uint32_t b0, b1v;
                asm volatile("ld.shared.b32 %0, [%1];" : "=r"(b0)  : "r"(ab0));
                asm volatile("ld.shared.b32 %0, [%1];" : "=r"(b1v) : "r"(ab1));
#pragma unroll
                for (int mt = 0; mt < 2; mt++) {
                    asm volatile(
                        "mma.sync.aligned.m16n8k16.row.col.f32.bf16.bf16.f32 "
                        "{%0,%1,%2,%3}, {%4,%5,%6,%7}, {%8,%9}, {%0,%1,%2,%3};"
                        : "+f"(acc[mt][nt][0]), "+f"(acc[mt][nt][1]),
                          "+f"(acc[mt][nt][2]), "+f"(acc[mt][nt][3])
                        : "r"(a[mt][0]), "r"(a[mt][1]), "r"(a[mt][2]), "r"(a[mt][3]),
                          "r"(b0), "r"(b1v));
                }
            }
        }
    }

    const float* bias = (const float*)(sm + BIAS_OFF);
#pragma unroll
    for (int mt = 0; mt < 2; mt++) {
        int px_a = px0 + warp*32 + mt*16 + g_;
#pragma unroll
        for (int nt = 0; nt < 8; nt++) {
            int n = nt*8 + tig*2;
            float bx = bias[n], by = bias[n+1];
            float* p0 = g_comp + ((size_t)b*HW_ + px_a) * COMP_ + n;
            *(float2*)p0             = make_float2(acc[mt][nt][0] + bx, acc[mt][nt][1] + by);
            *(float2*)(p0 + 8*COMP_) = make_float2(acc[mt][nt][2] + bx, acc[mt][nt][3] + by);
        }
    }
}

// ================= Kernel B: 3x3 stride-2 conv (64 -> 25) + fused softmax =================
#define CS_ROW   130
#define CS_CH    (5*CS_ROW)
#define WA_OFF   (COMP_*CS_CH)
#define WB_OFF   (WA_OFF + KK_*COMP_*8)
#define B_SMEM_FLOATS (WB_OFF + KK_*COMP_)
#define B_SMEM_BYTES (B_SMEM_FLOATS*4)

__global__ __launch_bounds__(256) void k_conv2(const float* __restrict__ w2,
                                               const float* __restrict__ b2) {
    extern __shared__ __align__(16) float smemB[];
    float* cs = smemB;
    float* wA = smemB + WA_OFF;
    float* wB = smemB + WB_OFF;
    float* ls = smemB;

    const int b   = blockIdx.y;
    const int hop = blockIdx.x;
    const int tid = threadIdx.x;

    for (int idx = tid; idx < KK_*COMP_*8; idx += 256) {
        int oc = idx >> 3, k = idx & 7;
        wA[idx] = w2[oc*9 + k];
    }
    for (int idx = tid; idx < KK_*COMP_; idx += 256)
        wB[idx] = w2[idx*9 + 8];

    const int r0 = 4*hop - 1;
    for (int idx = tid; idx < COMP_*CS_CH; idx += 256) {
        int c   = idx & 63;
        int pix = idx >> 6;
        int r   = pix / CS_ROW;
        int col = pix - r*CS_ROW;
        int gr = r0 + r, gc = col - 1;
        float v = 0.f;
        if ((unsigned)gr < (unsigned)H_ && (unsigned)gc < (unsigned)W_)
            v = g_comp[((size_t)b*HW_ + gr*W_ + gc) * COMP_ + c];
        cs[c*CS_CH + r*CS_ROW + col] = v;
    }
    __syncthreads();

    const int wo = tid & 63;
    const int og = tid >> 6;
    const int nO = (og == 0) ? 7 : 6;

    float acc0[7], acc1[7];
#pragma unroll
    for (int t = 0; t < 7; t++) { acc0[t] = 0.f; acc1[t] = 0.f; }

#pragma unroll 1
    for (int c = 0; c < COMP_; c++) {
        const float* csp = cs + c*CS_CH + 2*wo;
        float xv[5][3];
#pragma unroll
        for (int r = 0; r < 5; r++) {
            float2 u = *(const float2*)(csp + r*CS_ROW);
            xv[r][0] = u.x; xv[r][1] = u.y;
            xv[r][2] = csp[r*CS_ROW + 2];
        }
#pragma unroll
        for (int t = 0; t < 7; t++) {
            if (t < nO) {
                int o = og + 4*t;
                const float* wa = wA + (o*COMP_ + c)*8;
                float4 v0 = *(const float4*)wa;
                float4 v1 = *(const float4*)(wa + 4);
                float  w8 = wB[o*COMP_ + c];
                float a0 = acc0[t], a1 = acc1[t];
                a0 = fmaf(v0.x, xv[0][0], a0);  a1 = fmaf(v0.x, xv[2][0], a1);
                a0 = fmaf(v0.y, xv[0][1], a0);  a1 = fmaf(v0.y, xv[2][1], a1);
                a0 = fmaf(v0.z, xv[0][2], a0);  a1 = fmaf(v0.z, xv[2][2], a1);
                a0 = fmaf(v0.w, xv[1][0], a0);  a1 = fmaf(v0.w, xv[3][0], a1);
                a0 = fmaf(v1.x, xv[1][1], a0);  a1 = fmaf(v1.x, xv[3][1], a1);
                a0 = fmaf(v1.y, xv[1][2], a0);  a1 = fmaf(v1.y, xv[3][2], a1);
                a0 = fmaf(v1.z, xv[2][0], a0);  a1 = fmaf(v1.z, xv[4][0], a1);
                a0 = fmaf(v1.w, xv[2][1], a0);  a1 = fmaf(v1.w, xv[4][1], a1);
                a0 = fmaf(w8,   xv[2][2], a0);  a1 = fmaf(w8,   xv[4][2], a1);
                acc0[t] = a0; acc1[t] = a1;
            }
        }
    }

    __syncthreads();
#pragma unroll
    for (int t = 0; t < 7; t++) {
        if (t < nO) {
            int o = og + 4*t;
            float bias = b2[o];
            ls[(     wo)*29 + o] = acc0[t] + bias;
            ls[(64 + wo)*29 + o] = acc1[t] + bias;
        }
    }
    __syncthreads();

    const int ho0 = 2*hop;
    if (tid < 128) {
        const float* lp = ls + tid*29;
        float mx = -1e30f;
#pragma unroll
        for (int o = 0; o < KK_; o++) mx = fmaxf(mx, lp[o]);
        float e[KK_]; float s = 0.f;
#pragma unroll
        for (int o = 0; o < KK_; o++) { e[o] = __expf(lp[o] - mx); s += e[o]; }
        float inv = 1.f / s;
        int ho = ho0 + (tid >> 6);
        int wx = tid & 63;
#pragma unroll
        for (int o = 0; o < KK_; o++)
            g_mask[(((size_t)b*KK_ + o)*HO_ + ho)*WO_ + wx] = e[o] * inv;
    }
}

// ================= Kernel C: CARAFE gather from fp16 shadow =================
// grid (64 ho, 4 cq, 4 b), block 256 = (wo 64) x (slot 4). Warp = 32 consecutive wo.
__global__ __launch_bounds__(256, 4) void k_carafe(float* __restrict__ out) {
    __shared__ float ms[KK_*64];

    const int ho = blockIdx.x;
    const int cq = blockIdx.y;
    const int b  = blockIdx.z;
    const int tid = threadIdx.x;

    for (int idx = tid; idx < KK_*64; idx += 256)
        ms[idx] = g_mask[(((size_t)b*KK_ + (idx >> 6))*HO_ + ho)*WO_ + (idx & 63)];
    __syncthreads();

    const int wo   = tid & 63;
    const int slot = tid >> 6;

    float mw[KK_];
#pragma unroll
    for (int o = 0; o < KK_; o++) mw[o] = ms[o*64 + wo];

    const int r0 = 2*ho - 2;
    const int cL = 2*wo - 2;                       // even -> half2 aligned
    const bool okL = (wo > 0);
    const bool okR = (wo < 63);
    const __half2 zh = __float2half2_rn(0.f);

    const __half* xc = g_xh + ((size_t)(b*C_ + cq*64 + slot*16)) * HW_ + cL;
    float* ob = out + (((size_t)(b*C_ + cq*64 + slot*16))*HO_ + ho)*WO_ + wo;

#pragma unroll 2
    for (int t = 0; t < 16; t++) {
        float a = 0.f;
#pragma unroll
        for (int i = 0; i < 5; i++) {
            const int r = r0 + i;
            if ((unsigned)r < (unsigned)H_) {
                const __half2* p = (const __half2*)(xc + (size_t)r * W_);
                __half2 v01 = okL ? __ldg(p)     : zh;   // cols 2wo-2, 2wo-1
                __half2 v23 = __ldg(p + 1);              // cols 2wo,   2wo+1
                __half2 v45 = okR ? __ldg(p + 2) : zh;   // cols 2wo+2 (.x used)
                float2 f01 = __half22float2(v01);
                float2 f23 = __half22float2(v23);
                float  f4  = __low2float(v45);
                a = fmaf(mw[5*i+0], f01.x, a);
                a = fmaf(mw[5*i+1], f01.y, a);
                a = fmaf(mw[5*i+2], f23.x, a);
                a = fmaf(mw[5*i+3], f23.y, a);
                a = fmaf(mw[5*i+4], f4,    a);
            }
        }
        *ob = a;                                  // coalesced
        xc += HW_;
        ob += HO_*WO_;
    }
}

// ================= launch =================
extern "C" void kernel_launch(void* const* d_in, const int* in_sizes, int n_in,
                              void* d_out, int out_size) {
    const float* x  = (const float*)d_in[0];
    const float* w1 = (const float*)d_in[1];
    const float* b1 = (const float*)d_in[2];
    const float* w2 = (const float*)d_in[3];
    const float* b2 = (const float*)d_in[4];
    float* out = (float*)d_out;

    cudaFuncSetAttribute(k_conv1, cudaFuncAttributeMaxDynamicSharedMemorySize, A_SMEM_BYTES);
    cudaFuncSetAttribute(k_conv2, cudaFuncAttributeMaxDynamicSharedMemorySize, B_SMEM_BYTES);

    k_prep<<<64, 256>>>(w1);
    k_conv1<<<dim3(64, 4), 256, A_SMEM_BYTES>>>(x, b1);
    k_conv2<<<dim3(32, 4), 256, B_SMEM_BYTES>>>(w2, b2);
    k_carafe<<<dim3(64, 4, 4), 256>>>(out);
}

// round 9
// speedup vs baseline: 1.2303x; 1.2303x over previous
#include <cuda_runtime.h>
#include <cuda_bf16.h>
#include <cstdint>

#define B_    4
#define C_    256
#define H_    128
#define W_    128
#define HW_   (H_*W_)
#define COMP_ 64
#define KK_   25
#define HO_   64
#define WO_   64

// Scratch (device globals; allocation is forbidden)
// g_comp layout: [b][px (h*W+w)][ch]  (channel-minor!)
__device__ float g_comp[B_*HW_*COMP_];
__device__ float g_mask[B_*KK_*HO_*WO_];                    // NORMALIZED softmax weights
__device__ __align__(16) unsigned char g_w1b[COMP_*C_*2];   // w1 bf16, plain [n][k]

__device__ __forceinline__ uint32_t smem_u32(const void* p) {
    uint32_t a;
    asm("{ .reg .u64 t; cvta.to.shared.u64 t, %1; cvt.u32.u64 %0, t; }" : "=r"(a) : "l"(p));
    return a;
}

// ================= Kernel P: w1 fp32 -> bf16 =================
__global__ void k_prep(const float* __restrict__ w1) {
    int idx = blockIdx.x * 256 + threadIdx.x;
    if (idx < COMP_ * C_)
        ((__nv_bfloat16*)g_w1b)[idx] = __float2bfloat16(w1[idx]);
}

// ================= Kernel A: 1x1 conv via mma.sync bf16 =================
#define XS_OFF   0
#define WS_OFF   32768
#define BIAS_OFF 65536
#define A_SMEM_BYTES (65536 + 256)

__global__ __launch_bounds__(256) void k_conv1(const float* __restrict__ x,
                                               const float* __restrict__ b1) {
    extern __shared__ __align__(16) char sm[];
    const uint32_t smb = smem_u32(sm);
    const int tid  = threadIdx.x;
    const int warp = tid >> 5;
    const int lane = tid & 31;
    const int b    = blockIdx.y;
    const int px0  = blockIdx.x * 256;

    {
        const uint32_t* wsrc = (const uint32_t*)g_w1b;
        for (int i = tid; i < COMP_ * C_ / 2; i += 256) {
            int n = i >> 7, u = i & 127;
            int cx = u >> 2;
            uint32_t off = WS_OFF + n*512 + (uint32_t)((cx ^ (n & 7)) << 4) + (u & 3) * 4;
            *(uint32_t*)(sm + off) = wsrc[i];
        }
        if (tid < 64) ((float*)(sm + BIAS_OFF))[tid] = b1[tid];
    }

    float acc[2][8][4];
#pragma unroll
    for (int mt = 0; mt < 2; mt++)
#pragma unroll
        for (int nt = 0; nt < 8; nt++)
#pragma unroll
            for (int i = 0; i < 4; i++) acc[mt][nt][i] = 0.f;

    const int lj  = lane & 7;
    const int lg2 = (lane >> 3) & 1;
    const int lg4 = lane >> 4;
    const int g_  = lane >> 2;
    const int tig = lane & 3;

    const float* xbase = x + ((size_t)b * C_) * HW_ + px0;

    for (int chunk = 0; chunk < 4; chunk++) {
        __syncthreads();
        const float4* xsrc = (const float4*)(xbase + (size_t)(chunk * 64) * HW_);
#pragma unroll
        for (int l = 0; l < 16; l++) {
            int id = l * 256 + tid;
            int ch = id >> 6, f4 = id & 63;
            float4 v = xsrc[(size_t)ch * (HW_/4) + f4];
            __nv_bfloat162 h0 = __float22bfloat162_rn(make_float2(v.x, v.y));
            __nv_bfloat162 h1 = __float22bfloat162_rn(make_float2(v.z, v.w));
            int cx = f4 >> 1;
            uint32_t off = XS_OFF + ch*512 + (uint32_t)((cx ^ (ch & 7)) << 4) + (f4 & 1) * 8;
            *(uint2*)(sm + off) = make_uint2(*(uint32_t*)&h0, *(uint32_t*)&h1);
        }
        __syncthreads();

#pragma unroll
        for (int s = 0; s < 4; s++) {
            uint32_t a[2][4];
            const int krow = s*16 + lj + lg4*8;
#pragma unroll
            for (int mt = 0; mt < 2; mt++) {
                int pxcol = warp*32 + mt*16 + lg2*8;
                uint32_t addr = smb + XS_OFF + krow*512
                              + (uint32_t)(((pxcol >> 3) ^ (krow & 7)) << 4);
                asm volatile("ldmatrix.sync.aligned.m8n8.x4.trans.shared.b16 "
                             "{%0,%1,%2,%3}, [%4];"
                             : "=r"(a[mt][0]), "=r"(a[mt][1]), "=r"(a[mt][2]), "=r"(a[mt][3])
                             : "r"(addr));
            }
            const int kabs = chunk*64 + s*16;
            const int cx0  = kabs >> 3;
#pragma unroll
            for (int nt = 0; nt < 8; nt++) {
                int n = nt*8 + g_;
                uint32_t ab0 = smb + WS_OFF + n*512
                             + (uint32_t)(((cx0     ) ^ (n & 7)) << 4) + tig*4;
                uint32_t ab1 = smb + WS_OFF + n*512
                             + (uint32_t)(((cx0 + 1) ^ (n & 7)) << 4) + tig*4;
                uint32_t b0, b1v;
                asm volatile("ld.shared.b32 %0, [%1];" : "=r"(b0)  : "r"(ab0));
                asm volatile("ld.shared.b32 %0, [%1];" : "=r"(b1v) : "r"(ab1));
#pragma unroll
                for (int mt = 0; mt < 2; mt++) {
                    asm volatile(
                        "mma.sync.aligned.m16n8k16.row.col.f32.bf16.bf16.f32 "
                        "{%0,%1,%2,%3}, {%4,%5,%6,%7}, {%8,%9}, {%0,%1,%2,%3};"
                        : "+f"(acc[mt][nt][0]), "+f"(acc[mt][nt][1]),
                          "+f"(acc[mt][nt][2]), "+f"(acc[mt][nt][3])
                        : "r"(a[mt][0]), "r"(a[mt][1]), "r"(a[mt][2]), "r"(a[mt][3]),
                          "r"(b0), "r"(b1v));
                }
            }
        }
    }

    const float* bias = (const float*)(sm + BIAS_OFF);
#pragma unroll
    for (int mt = 0; mt < 2; mt++) {
        int px_a = px0 + warp*32 + mt*16 + g_;
#pragma unroll
        for (int nt = 0; nt < 8; nt++) {
            int n = nt*8 + tig*2;
            float bx = bias[n], by = bias[n+1];
            float* p0 = g_comp + ((size_t)b*HW_ + px_a) * COMP_ + n;
            *(float2*)p0             = make_float2(acc[mt][nt][0] + bx, acc[mt][nt][1] + by);
            *(float2*)(p0 + 8*COMP_) = make_float2(acc[mt][nt][2] + bx, acc[mt][nt][3] + by);
        }
    }
}

// ================= Kernel B: 3x3 stride-2 conv (64 -> 25) + fused softmax =================
#define CS_ROW   130
#define CS_CH    (5*CS_ROW)
#define WA_OFF   (COMP_*CS_CH)
#define WB_OFF   (WA_OFF + KK_*COMP_*8)
#define B_SMEM_FLOATS (WB_OFF + KK_*COMP_)
#define B_SMEM_BYTES (B_SMEM_FLOATS*4)

__global__ __launch_bounds__(256) void k_conv2(const float* __restrict__ w2,
                                               const float* __restrict__ b2) {
    extern __shared__ __align__(16) float smemB[];
    float* cs = smemB;
    float* wA = smemB + WA_OFF;
    float* wB = smemB + WB_OFF;
    float* ls = smemB;

    const int b   = blockIdx.y;
    const int hop = blockIdx.x;
    const int tid = threadIdx.x;

    for (int idx = tid; idx < KK_*COMP_*8; idx += 256) {
        int oc = idx >> 3, k = idx & 7;
        wA[idx] = w2[oc*9 + k];
    }
    for (int idx = tid; idx < KK_*COMP_; idx += 256)
        wB[idx] = w2[idx*9 + 8];

    const int r0 = 4*hop - 1;
    for (int idx = tid; idx < COMP_*CS_CH; idx += 256) {
        int c   = idx & 63;
        int pix = idx >> 6;
        int r   = pix / CS_ROW;
        int col = pix - r*CS_ROW;
        int gr = r0 + r, gc = col - 1;
        float v = 0.f;
        if ((unsigned)gr < (unsigned)H_ && (unsigned)gc < (unsigned)W_)
            v = g_comp[((size_t)b*HW_ + gr*W_ + gc) * COMP_ + c];
        cs[c*CS_CH + r*CS_ROW + col] = v;
    }
    __syncthreads();

    const int wo = tid & 63;
    const int og = tid >> 6;
    const int nO = (og == 0) ? 7 : 6;

    float acc0[7], acc1[7];
#pragma unroll
    for (int t = 0; t < 7; t++) { acc0[t] = 0.f; acc1[t] = 0.f; }

#pragma unroll 1
    for (int c = 0; c < COMP_; c++) {
        const float* csp = cs + c*CS_CH + 2*wo;
        float xv[5][3];
#pragma unroll
        for (int r = 0; r < 5; r++) {
            float2 u = *(const float2*)(csp + r*CS_ROW);
            xv[r][0] = u.x; xv[r][1] = u.y;
            xv[r][2] = csp[r*CS_ROW + 2];
        }
#pragma unroll
        for (int t = 0; t < 7; t++) {
            if (t < nO) {
                int o = og + 4*t;
                const float* wa = wA + (o*COMP_ + c)*8;
                float4 v0 = *(const float4*)wa;
                float4 v1 = *(const float4*)(wa + 4);
                float  w8 = wB[o*COMP_ + c];
                float a0 = acc0[t], a1 = acc1[t];
                a0 = fmaf(v0.x, xv[0][0], a0);  a1 = fmaf(v0.x, xv[2][0], a1);
                a0 = fmaf(v0.y, xv[0][1], a0);  a1 = fmaf(v0.y, xv[2][1], a1);
                a0 = fmaf(v0.z, xv[0][2], a0);  a1 = fmaf(v0.z, xv[2][2], a1);
                a0 = fmaf(v0.w, xv[1][0], a0);  a1 = fmaf(v0.w, xv[3][0], a1);
                a0 = fmaf(v1.x, xv[1][1], a0);  a1 = fmaf(v1.x, xv[3][1], a1);
                a0 = fmaf(v1.y, xv[1][2], a0);  a1 = fmaf(v1.y, xv[3][2], a1);
                a0 = fmaf(v1.z, xv[2][0], a0);  a1 = fmaf(v1.z, xv[4][0], a1);
                a0 = fmaf(v1.w, xv[2][1], a0);  a1 = fmaf(v1.w, xv[4][1], a1);
                a0 = fmaf(w8,   xv[2][2], a0);  a1 = fmaf(w8,   xv[4][2], a1);
                acc0[t] = a0; acc1[t] = a1;
            }
        }
    }

    __syncthreads();
#pragma unroll
    for (int t = 0; t < 7; t++) {
        if (t < nO) {
            int o = og + 4*t;
            float bias = b2[o];
            ls[(     wo)*29 + o] = acc0[t] + bias;
            ls[(64 + wo)*29 + o] = acc1[t] + bias;
        }
    }
    __syncthreads();

    const int ho0 = 2*hop;
    if (tid < 128) {
        const float* lp = ls + tid*29;
        float mx = -1e30f;
#pragma unroll
        for (int o = 0; o < KK_; o++) mx = fmaxf(mx, lp[o]);
        float e[KK_]; float s = 0.f;
#pragma unroll
        for (int o = 0; o < KK_; o++) { e[o] = __expf(lp[o] - mx); s += e[o]; }
        float inv = 1.f / s;
        int ho = ho0 + (tid >> 6);
        int wx = tid & 63;
#pragma unroll
        for (int o = 0; o < KK_; o++)
            g_mask[(((size_t)b*KK_ + o)*HO_ + ho)*WO_ + wx] = e[o] * inv;
    }
}

// ================= Kernel C: CARAFE gather — software-pipelined =================
// grid (64 ho, 4 cq, 4 b), block 256 = (wo 64) x (slot 4).
// Loads for channel t+1 issue BEFORE the FMA chain of channel t (breaks the
// long-scoreboard serialization). Weights read from smem (conflict-free LDS)
// instead of 25 registers, paying ILP-hidden LDS latency for occupancy.
__global__ __launch_bounds__(256) void k_carafe(const float* __restrict__ x,
                                                float* __restrict__ out) {
    __shared__ float ms[KK_*64];

    const int ho = blockIdx.x;
    const int cq = blockIdx.y;
    const int b  = blockIdx.z;
    const int tid = threadIdx.x;

    for (int idx = tid; idx < KK_*64; idx += 256)
        ms[idx] = g_mask[(((size_t)b*KK_ + (idx >> 6))*HO_ + ho)*WO_ + (idx & 63)];
    __syncthreads();

    const int wo   = tid & 63;
    const int slot = tid >> 6;
    const float* mp = ms + wo;            // weight o at mp[o*64]; warp stride-1, conflict-free

    const int r0 = 2*ho - 2;
    const int cL = 2*wo - 2;              // even -> 8B aligned
    const bool okL = (wo > 0);
    const bool okR = (wo < 63);
    const float2 z2 = make_float2(0.f, 0.f);

    // row validity is channel-invariant: precompute
    bool rok[5];
#pragma unroll
    for (int i = 0; i < 5; i++) { int r = r0 + i; rok[i] = ((unsigned)r < (unsigned)H_); }

    const float* xc = x + ((size_t)(b*C_ + cq*64 + slot*16)) * HW_ + cL;
    float* ob = out + (((size_t)(b*C_ + cq*64 + slot*16))*HO_ + ho)*WO_ + wo;

    float2 a01[5], a23[5]; float a4[5];
    // prefetch channel 0
#pragma unroll
    for (int i = 0; i < 5; i++) {
        const float* base = xc + (size_t)(r0 + i) * W_;
        a01[i] = (rok[i] && okL) ? __ldg((const float2*)base)       : z2;
        a23[i] =  rok[i]         ? __ldg((const float2*)(base + 2)) : z2;
        a4[i]  = (rok[i] && okR) ? __ldg(base + 4)                  : 0.f;
    }

#pragma unroll 1
    for (int t = 0; t < 16; t++) {
        // ---- issue loads for channel t+1 FIRST (overlap with FMAs below) ----
        const float* xn = xc + (t < 15 ? HW_ : 0);      // clamp keeps address valid
        float2 b01[5], b23[5]; float b4[5];
#pragma unroll
        for (int i = 0; i < 5; i++) {
            const float* base = xn + (size_t)(r0 + i) * W_;
            b01[i] = (rok[i] && okL) ? __ldg((const float2*)base)       : z2;
            b23[i] =  rok[i]         ? __ldg((const float2*)(base + 2)) : z2;
            b4[i]  = (rok[i] && okR) ? __ldg(base + 4)                  : 0.f;
        }

        // ---- consume channel t (weights via LDS) ----
        float a = 0.f;
#pragma unroll
        for (int i = 0; i < 5; i++) {
            a = fmaf(mp[(5*i+0)*64], a01[i].x, a);
            a = fmaf(mp[(5*i+1)*64], a01[i].y, a);
            a = fmaf(mp[(5*i+2)*64], a23[i].x, a);
            a = fmaf(mp[(5*i+3)*64], a23[i].y, a);
            a = fmaf(mp[(5*i+4)*64], a4[i],    a);
        }
        *ob = a;                                        // coalesced

        // rotate buffers
#pragma unroll
        for (int i = 0; i < 5; i++) { a01[i] = b01[i]; a23[i] = b23[i]; a4[i] = b4[i]; }
        xc += HW_;
        ob += HO_*WO_;
    }
}

// ================= launch =================
extern "C" void kernel_launch(void* const* d_in, const int* in_sizes, int n_in,
                              void* d_out, int out_size) {
    const float* x  = (const float*)d_in[0];
    const float* w1 = (const float*)d_in[1];
    const float* b1 = (const float*)d_in[2];
    const float* w2 = (const float*)d_in[3];
    const float* b2 = (const float*)d_in[4];
    float* out = (float*)d_out;

    cudaFuncSetAttribute(k_conv1, cudaFuncAttributeMaxDynamicSharedMemorySize, A_SMEM_BYTES);
    cudaFuncSetAttribute(k_conv2, cudaFuncAttributeMaxDynamicSharedMemorySize, B_SMEM_BYTES);

    k_prep<<<64, 256>>>(w1);
    k_conv1<<<dim3(64, 4), 256, A_SMEM_BYTES>>>(x, b1);
    k_conv2<<<dim3(32, 4), 256, B_SMEM_BYTES>>>(w2, b2);
    k_carafe<<<dim3(64, 4, 4), 256>>>(x, out);
}

// round 10
// speedup vs baseline: 1.2485x; 1.0149x over previous
#include <cuda_runtime.h>
#include <cuda_bf16.h>
#include <cstdint>

#define B_    4
#define C_    256
#define H_    128
#define W_    128
#define HW_   (H_*W_)
#define COMP_ 64
#define KK_   25
#define HO_   64
#define WO_   64

// Scratch (device globals; allocation is forbidden)
// g_comp layout: [b][px (h*W+w)][ch]  (channel-minor!)
__device__ float g_comp[B_*HW_*COMP_];
__device__ float g_mask[B_*KK_*HO_*WO_];                    // NORMALIZED softmax weights
__device__ __align__(16) unsigned char g_w1b[COMP_*C_*2];   // w1 bf16, plain [n][k]

__device__ __forceinline__ uint32_t smem_u32(const void* p) {
    uint32_t a;
    asm("{ .reg .u64 t; cvta.to.shared.u64 t, %1; cvt.u32.u64 %0, t; }" : "=r"(a) : "l"(p));
    return a;
}

// ================= Kernel P: w1 fp32 -> bf16 =================
__global__ void k_prep(const float* __restrict__ w1) {
    int idx = blockIdx.x * 256 + threadIdx.x;
    if (idx < COMP_ * C_)
        ((__nv_bfloat16*)g_w1b)[idx] = __float2bfloat16(w1[idx]);
}

// ================= Kernel A: 1x1 conv via mma.sync bf16 (64-px tiles) =================
// grid (256, 4) = 1024 CTAs, block 128 (4 warps x 16 px). Near-perfect wave balance.
// smem: xs bf16 [64ch][64px] swizzled (8KB) | ws bf16 [64n][256k] swizzled (32KB) | bias
#define XS_OFF   0
#define WS_OFF   8192
#define BIAS_OFF (8192 + 32768)
#define A_SMEM_BYTES (BIAS_OFF + 256)

__global__ __launch_bounds__(128) void k_conv1(const float* __restrict__ x,
                                               const float* __restrict__ b1) {
    extern __shared__ __align__(16) char sm[];
    const uint32_t smb = smem_u32(sm);
    const int tid  = threadIdx.x;
    const int warp = tid >> 5;
    const int lane = tid & 31;
    const int b    = blockIdx.y;
    const int px0  = blockIdx.x * 64;

    // ws: 2048 16B-chunks, chunk cx of row n stored at n*512 + ((cx^(n&7))<<4)
    {
        const uint4* wsrc = (const uint4*)g_w1b;
#pragma unroll
        for (int l = 0; l < 16; l++) {
            int i = l*128 + tid;
            int n = i >> 5, cx = i & 31;
            *(uint4*)(sm + WS_OFF + n*512 + (uint32_t)((cx ^ (n & 7)) << 4)) = wsrc[i];
        }
        if (tid < 64) ((float*)(sm + BIAS_OFF))[tid] = b1[tid];
    }

    float acc[8][4];
#pragma unroll
    for (int nt = 0; nt < 8; nt++)
#pragma unroll
        for (int i = 0; i < 4; i++) acc[nt][i] = 0.f;

    const int lj  = lane & 7;
    const int lg2 = (lane >> 3) & 1;
    const int lg4 = lane >> 4;
    const int g_  = lane >> 2;
    const int tig = lane & 3;

    const float* xbase = x + ((size_t)b * C_) * HW_ + px0;

    for (int chunk = 0; chunk < 4; chunk++) {
        __syncthreads();
        // load 64 ch x 64 px fp32 -> bf16 swizzled xs (rows 128B, 8 chunks)
        const float4* xsrc = (const float4*)(xbase + (size_t)(chunk * 64) * HW_);
#pragma unroll
        for (int l = 0; l < 8; l++) {
            int id = l*128 + tid;
            int ch = id >> 4, f4 = id & 15;
            float4 v = xsrc[(size_t)ch * (HW_/4) + f4];
            __nv_bfloat162 h0 = __float22bfloat162_rn(make_float2(v.x, v.y));
            __nv_bfloat162 h1 = __float22bfloat162_rn(make_float2(v.z, v.w));
            int cx = f4 >> 1;
            uint32_t off = XS_OFF + ch*128 + (uint32_t)((cx ^ (ch & 7)) << 4) + (f4 & 1) * 8;
            *(uint2*)(sm + off) = make_uint2(*(uint32_t*)&h0, *(uint32_t*)&h1);
        }
        __syncthreads();

#pragma unroll
        for (int s = 0; s < 4; s++) {
            uint32_t a[4];
            const int krow  = s*16 + lj + lg4*8;
            const int pxcol = warp*16 + lg2*8;
            uint32_t addr = smb + XS_OFF + krow*128
                          + (uint32_t)(((pxcol >> 3) ^ (krow & 7)) << 4);
            asm volatile("ldmatrix.sync.aligned.m8n8.x4.trans.shared.b16 "
                         "{%0,%1,%2,%3}, [%4];"
                         : "=r"(a[0]), "=r"(a[1]), "=r"(a[2]), "=r"(a[3])
                         : "r"(addr));
            const int kabs = chunk*64 + s*16;
            const int cx0  = kabs >> 3;
#pragma unroll
            for (int nt = 0; nt < 8; nt++) {
                int n = nt*8 + g_;
                uint32_t ab0 = smb + WS_OFF + n*512
                             + (uint32_t)(((cx0     ) ^ (n & 7)) << 4) + tig*4;
                uint32_t ab1 = smb + WS_OFF + n*512
                             + (uint32_t)(((cx0 + 1) ^ (n & 7)) << 4) + tig*4;
                uint32_t b0, b1v;
                asm volatile("ld.shared.b32 %0, [%1];" : "=r"(b0)  : "r"(ab0));
                asm volatile("ld.shared.b32 %0, [%1];" : "=r"(b1v) : "r"(ab1));
                asm volatile(
                    "mma.sync.aligned.m16n8k16.row.col.f32.bf16.bf16.f32 "
                    "{%0,%1,%2,%3}, {%4,%5,%6,%7}, {%8,%9}, {%0,%1,%2,%3};"
                    : "+f"(acc[nt][0]), "+f"(acc[nt][1]),
                      "+f"(acc[nt][2]), "+f"(acc[nt][3])
                    : "r"(a[0]), "r"(a[1]), "r"(a[2]), "r"(a[3]),
                      "r"(b0), "r"(b1v));
            }
        }
    }

    const float* bias = (const float*)(sm + BIAS_OFF);
    const int px_a = px0 + warp*16 + g_;
#pragma unroll
    for (int nt = 0; nt < 8; nt++) {
        int n = nt*8 + tig*2;
        float bx = bias[n], by = bias[n+1];
        float* p0 = g_comp + ((size_t)b*HW_ + px_a) * COMP_ + n;
        *(float2*)p0             = make_float2(acc[nt][0] + bx, acc[nt][1] + by);
        *(float2*)(p0 + 8*COMP_) = make_float2(acc[nt][2] + bx, acc[nt][3] + by);
    }
}

// ================= Kernel B: 3x3 stride-2 conv (64 -> 25) + fused softmax =================
#define CS_ROW   130
#define CS_CH    (5*CS_ROW)
#define WA_OFF   (COMP_*CS_CH)
#define WB_OFF   (WA_OFF + KK_*COMP_*8)
#define B_SMEM_FLOATS (WB_OFF + KK_*COMP_)
#define B_SMEM_BYTES (B_SMEM_FLOATS*4)

__global__ __launch_bounds__(256) void k_conv2(const float* __restrict__ w2,
                                               const float* __restrict__ b2) {
    extern __shared__ __align__(16) float smemB[];
    float* cs = smemB;
    float* wA = smemB + WA_OFF;
    float* wB = smemB + WB_OFF;
    float* ls = smemB;

    const int b   = blockIdx.y;
    const int hop = blockIdx.x;
    const int tid = threadIdx.x;

    for (int idx = tid; idx < KK_*COMP_*8; idx += 256) {
        int oc = idx >> 3, k = idx & 7;
        wA[idx] = w2[oc*9 + k];
    }
    for (int idx = tid; idx < KK_*COMP_; idx += 256)
        wB[idx] = w2[idx*9 + 8];

    const int r0 = 4*hop - 1;
    for (int idx = tid; idx < COMP_*CS_CH; idx += 256) {
        int c   = idx & 63;
        int pix = idx >> 6;
        int r   = pix / CS_ROW;
        int col = pix - r*CS_ROW;
        int gr = r0 + r, gc = col - 1;
        float v = 0.f;
        if ((unsigned)gr < (unsigned)H_ && (unsigned)gc < (unsigned)W_)
            v = g_comp[((size_t)b*HW_ + gr*W_ + gc) * COMP_ + c];
        cs[c*CS_CH + r*CS_ROW + col] = v;
    }
    __syncthreads();

    const int wo = tid & 63;
    const int og = tid >> 6;
    const int nO = (og == 0) ? 7 : 6;

    float acc0[7], acc1[7];
#pragma unroll
    for (int t = 0; t < 7; t++) { acc0[t] = 0.f; acc1[t] = 0.f; }

#pragma unroll 1
    for (int c = 0; c < COMP_; c++) {
        const float* csp = cs + c*CS_CH + 2*wo;
        float xv[5][3];
#pragma unroll
        for (int r = 0; r < 5; r++) {
            float2 u = *(const float2*)(csp + r*CS_ROW);
            xv[r][0] = u.x; xv[r][1] = u.y;
            xv[r][2] = csp[r*CS_ROW + 2];
        }
#pragma unroll
        for (int t = 0; t < 7; t++) {
            if (t < nO) {
                int o = og + 4*t;
                const float* wa = wA + (o*COMP_ + c)*8;
                float4 v0 = *(const float4*)wa;
                float4 v1 = *(const float4*)(wa + 4);
                float  w8 = wB[o*COMP_ + c];
                float a0 = acc0[t], a1 = acc1[t];
                a0 = fmaf(v0.x, xv[0][0], a0);  a1 = fmaf(v0.x, xv[2][0], a1);
                a0 = fmaf(v0.y, xv[0][1], a0);  a1 = fmaf(v0.y, xv[2][1], a1);
                a0 = fmaf(v0.z, xv[0][2], a0);  a1 = fmaf(v0.z, xv[2][2], a1);
                a0 = fmaf(v0.w, xv[1][0], a0);  a1 = fmaf(v0.w, xv[3][0], a1);
                a0 = fmaf(v1.x, xv[1][1], a0);  a1 = fmaf(v1.x, xv[3][1], a1);
                a0 = fmaf(v1.y, xv[1][2], a0);  a1 = fmaf(v1.y, xv[3][2], a1);
                a0 = fmaf(v1.z, xv[2][0], a0);  a1 = fmaf(v1.z, xv[4][0], a1);
                a0 = fmaf(v1.w, xv[2][1], a0);  a1 = fmaf(v1.w, xv[4][1], a1);
                a0 = fmaf(w8,   xv[2][2], a0);  a1 = fmaf(w8,   xv[4][2], a1);
                acc0[t] = a0; acc1[t] = a1;
            }
        }
    }

    __syncthreads();
#pragma unroll
    for (int t = 0; t < 7; t++) {
        if (t < nO) {
            int o = og + 4*t;
            float bias = b2[o];
            ls[(     wo)*29 + o] = acc0[t] + bias;
            ls[(64 + wo)*29 + o] = acc1[t] + bias;
        }
    }
    __syncthreads();

    const int ho0 = 2*hop;
    if (tid < 128) {
        const float* lp = ls + tid*29;
        float mx = -1e30f;
#pragma unroll
        for (int o = 0; o < KK_; o++) mx = fmaxf(mx, lp[o]);
        float e[KK_]; float s = 0.f;
#pragma unroll
        for (int o = 0; o < KK_; o++) { e[o] = __expf(lp[o] - mx); s += e[o]; }
        float inv = 1.f / s;
        int ho = ho0 + (tid >> 6);
        int wx = tid & 63;
#pragma unroll
        for (int o = 0; o < KK_; o++)
            g_mask[(((size_t)b*KK_ + o)*HO_ + ho)*WO_ + wx] = e[o] * inv;
    }
}

// ================= Kernel C: CARAFE gather — pipelined, weights in registers =================
// grid (64 ho, 4 cq, 4 b), block 256 = (wo 64) x (slot 4).
__global__ __launch_bounds__(256) void k_carafe(const float* __restrict__ x,
                                                float* __restrict__ out) {
    __shared__ float ms[KK_*64];

    const int ho = blockIdx.x;
    const int cq = blockIdx.y;
    const int b  = blockIdx.z;
    const int tid = threadIdx.x;

    for (int idx = tid; idx < KK_*64; idx += 256)
        ms[idx] = g_mask[(((size_t)b*KK_ + (idx >> 6))*HO_ + ho)*WO_ + (idx & 63)];
    __syncthreads();

    const int wo   = tid & 63;
    const int slot = tid >> 6;

    // weights in registers: no per-channel LDS traffic
    float mw[KK_];
#pragma unroll
    for (int o = 0; o < KK_; o++) mw[o] = ms[o*64 + wo];

    const int r0 = 2*ho - 2;
    const int cL = 2*wo - 2;              // even -> 8B aligned
    const bool okL = (wo > 0);
    const bool okR = (wo < 63);
    const float2 z2 = make_float2(0.f, 0.f);

    bool rok[5];
#pragma unroll
    for (int i = 0; i < 5; i++) { int r = r0 + i; rok[i] = ((unsigned)r < (unsigned)H_); }

    const float* xc = x + ((size_t)(b*C_ + cq*64 + slot*16)) * HW_ + cL;
    float* ob = out + (((size_t)(b*C_ + cq*64 + slot*16))*HO_ + ho)*WO_ + wo;

    float2 a01[5], a23[5]; float a4[5];
#pragma unroll
    for (int i = 0; i < 5; i++) {
        const float* base = xc + (size_t)(r0 + i) * W_;
        a01[i] = (rok[i] && okL) ? __ldg((const float2*)base)       : z2;
        a23[i] =  rok[i]         ? __ldg((const float2*)(base + 2)) : z2;
        a4[i]  = (rok[i] && okR) ? __ldg(base + 4)                  : 0.f;
    }

#pragma unroll 1
    for (int t = 0; t < 16; t++) {
        // issue loads for channel t+1 first (overlaps the FMA chain below)
        const float* xn = xc + (t < 15 ? HW_ : 0);
        float2 b01[5], b23[5]; float b4[5];
#pragma unroll
        for (int i = 0; i < 5; i++) {
            const float* base = xn + (size_t)(r0 + i) * W_;
            b01[i] = (rok[i] && okL) ? __ldg((const float2*)base)       : z2;
            b23[i] =  rok[i]         ? __ldg((const float2*)(base + 2)) : z2;
            b4[i]  = (rok[i] && okR) ? __ldg(base + 4)                  : 0.f;
        }

        float a = 0.f;
#pragma unroll
        for (int i = 0; i < 5; i++) {
            a = fmaf(mw[5*i+0], a01[i].x, a);
            a = fmaf(mw[5*i+1], a01[i].y, a);
            a = fmaf(mw[5*i+2], a23[i].x, a);
            a = fmaf(mw[5*i+3], a23[i].y, a);
            a = fmaf(mw[5*i+4], a4[i],    a);
        }
        *ob = a;

#pragma unroll
        for (int i = 0; i < 5; i++) { a01[i] = b01[i]; a23[i] = b23[i]; a4[i] = b4[i]; }
        xc += HW_;
        ob += HO_*WO_;
    }
}

// ================= launch =================
extern "C" void kernel_launch(void* const* d_in, const int* in_sizes, int n_in,
                              void* d_out, int out_size) {
    const float* x  = (const float*)d_in[0];
    const float* w1 = (const float*)d_in[1];
    const float* b1 = (const float*)d_in[2];
    const float* w2 = (const float*)d_in[3];
    const float* b2 = (const float*)d_in[4];
    float* out = (float*)d_out;

    cudaFuncSetAttribute(k_conv1, cudaFuncAttributeMaxDynamicSharedMemorySize, A_SMEM_BYTES);
    cudaFuncSetAttribute(k_conv2, cudaFuncAttributeMaxDynamicSharedMemorySize, B_SMEM_BYTES);

    k_prep<<<64, 256>>>(w1);
    k_conv1<<<dim3(256, 4), 128, A_SMEM_BYTES>>>(x, b1);
    k_conv2<<<dim3(32, 4), 256, B_SMEM_BYTES>>>(w2, b2);
    k_carafe<<<dim3(64, 4, 4), 256>>>(x, out);
}